// round 1
// baseline (speedup 1.0000x reference)
#include <cuda_runtime.h>
#include <cuda_bf16.h>
#include <math.h>

// ---------------- problem constants ----------------
#define EMBED   1024
#define NHEADS  16
#define HDIM    64
#define SCALE   0.125f           // 64^-0.5
#define NQ      100
#define NPATCH  1024
#define SEQ     1124             // NPATCH + NQ
#define SEQP    1152             // SEQ padded to multiple of 8 (and 128B-ish)
#define BATCH   8
#define MTOT    (BATCH*SEQ)      // 8992
#define MLPH    4096
#define LN_EPS  1e-6f
#define NEG_BIG (-1.0e9f)

// ---------------- scratch (static device allocs are the sanctioned path) ----
__device__ float g_xn   [(MTOT+64)*EMBED];      // ln1 out -> later reused as attn_out
__device__ float g_qkv  [(MTOT+64)*3*EMBED];    // qkv; +64 row pad for padded-K V reads; later reused as ln2 out
__device__ float g_scores[(long)BATCH*NHEADS*SEQ*SEQP]; // attention scores / probs
__device__ float g_h1   [(long)MTOT*MLPH];      // mlp hidden
__device__ float g_xmid [(long)MTOT*EMBED];     // x + proj(attn)

// ---------------- small reductions ----------------
__device__ __forceinline__ float warpSum(float v){
    #pragma unroll
    for (int o = 16; o > 0; o >>= 1) v += __shfl_xor_sync(0xffffffffu, v, o);
    return v;
}
__device__ __forceinline__ float warpMax(float v){
    #pragma unroll
    for (int o = 16; o > 0; o >>= 1) v = fmaxf(v, __shfl_xor_sync(0xffffffffu, v, o));
    return v;
}

// ---------------- LayerNorm: one block per row (1024 elems, 256 thr) -------
__global__ void ln_kernel(const float* __restrict__ x,
                          const float* __restrict__ gamma,
                          const float* __restrict__ beta,
                          float* __restrict__ out)
{
    const int row = blockIdx.x;
    const int tid = threadIdx.x;
    const float4 v = reinterpret_cast<const float4*>(x + (size_t)row*EMBED)[tid];
    float s  = v.x + v.y + v.z + v.w;
    float ss = v.x*v.x + v.y*v.y + v.z*v.z + v.w*v.w;
    s = warpSum(s); ss = warpSum(ss);
    __shared__ float sh1[8], sh2[8];
    const int w = tid >> 5, l = tid & 31;
    if (l == 0) { sh1[w] = s; sh2[w] = ss; }
    __syncthreads();
    if (w == 0) {
        float a = (l < 8) ? sh1[l] : 0.f;
        float b = (l < 8) ? sh2[l] : 0.f;
        a = warpSum(a); b = warpSum(b);
        if (l == 0) { sh1[0] = a; sh2[0] = b; }
    }
    __syncthreads();
    const float mean = sh1[0] * (1.0f/EMBED);
    const float var  = sh2[0] * (1.0f/EMBED) - mean*mean;
    const float rstd = rsqrtf(var + LN_EPS);
    const float4 g4 = reinterpret_cast<const float4*>(gamma)[tid];
    const float4 b4 = reinterpret_cast<const float4*>(beta )[tid];
    float4 o;
    o.x = (v.x - mean)*rstd*g4.x + b4.x;
    o.y = (v.y - mean)*rstd*g4.y + b4.y;
    o.z = (v.z - mean)*rstd*g4.z + b4.z;
    o.w = (v.w - mean)*rstd*g4.w + b4.w;
    reinterpret_cast<float4*>(out + (size_t)row*EMBED)[tid] = o;
}

// ---------------- generic guarded batched SGEMM ----------------------------
// C[m,n] = epi( sum_k A[m,k]*B[k,n] )
// TB=true means B is given as Bp[n*ldb + k] (i.e. B^T stored row-major).
// EPI: 0 -> alpha*acc ; 1 -> acc + bias[n] + res[m*ldd+n] ; 2 -> gelu(acc+bias[n])
template<int BM,int BN,int BK,int TM,int TN,bool TB,int EPI>
__global__ void __launch_bounds__((BM/TM)*(BN/TN))
sgemm(const float* __restrict__ Ab, const float* __restrict__ Bb,
      const float* __restrict__ bias, const float* __restrict__ res,
      float* __restrict__ Db,
      int M, int N, int K, int lda, int ldb, int ldd,
      long sAb, long sAh, long sBb, long sBh, long sDb, long sDh,
      float alpha)
{
    constexpr int THREADS = (BM/TM)*(BN/TN);
    __shared__ float As[BK][BM];
    __shared__ float Bs[BK][BN];

    const int tid = threadIdx.x;
    const int z   = blockIdx.z;
    const float* A = Ab + (long)(z >> 4) * sAb + (long)(z & 15) * sAh;
    const float* B = Bb + (long)(z >> 4) * sBb + (long)(z & 15) * sBh;
    float*       D = Db + (long)(z >> 4) * sDb + (long)(z & 15) * sDh;

    const int m0 = blockIdx.y * BM;
    const int n0 = blockIdx.x * BN;

    // A staging indices: float4 along K, BM*BK == THREADS*4
    const int arow = tid / (BK/4);
    const int acol = (tid % (BK/4)) * 4;

    const int tx = tid % (BN/TN);
    const int ty = tid / (BN/TN);

    float acc[TM][TN];
    #pragma unroll
    for (int i = 0; i < TM; i++)
        #pragma unroll
        for (int j = 0; j < TN; j++) acc[i][j] = 0.f;

    const int nk = K / BK;
    for (int kt = 0; kt < nk; kt++) {
        const int k0 = kt * BK;
        // ---- stage A (transposed into As[k][m]) ----
        {
            float4 v = make_float4(0.f, 0.f, 0.f, 0.f);
            if (m0 + arow < M)
                v = *reinterpret_cast<const float4*>(A + (long)(m0 + arow)*lda + k0 + acol);
            As[acol+0][arow] = v.x; As[acol+1][arow] = v.y;
            As[acol+2][arow] = v.z; As[acol+3][arow] = v.w;
        }
        // ---- stage B ----
        if (!TB) {
            #pragma unroll
            for (int idx = tid; idx < BK*BN; idx += THREADS) {
                const int k = idx / BN, n = idx % BN;
                float v = 0.f;
                if (n0 + n < N) v = B[(long)(k0 + k)*ldb + (n0 + n)];
                Bs[k][n] = v;
            }
        } else {
            #pragma unroll
            for (int idx = tid; idx < BK*BN; idx += THREADS) {
                const int n = idx / BK, k = idx % BK;
                float v = 0.f;
                if (n0 + n < N) v = B[(long)(n0 + n)*ldb + (k0 + k)];
                Bs[k][n] = v;
            }
        }
        __syncthreads();

        #pragma unroll
        for (int k = 0; k < BK; k++) {
            float rA[TM], rB[TN];
            #pragma unroll
            for (int i = 0; i < TM; i++) rA[i] = As[k][ty*TM + i];
            #pragma unroll
            for (int j = 0; j < TN; j++) rB[j] = Bs[k][tx*TN + j];
            #pragma unroll
            for (int i = 0; i < TM; i++)
                #pragma unroll
                for (int j = 0; j < TN; j++)
                    acc[i][j] = fmaf(rA[i], rB[j], acc[i][j]);
        }
        __syncthreads();
    }

    // ---- epilogue ----
    #pragma unroll
    for (int i = 0; i < TM; i++) {
        const int m = m0 + ty*TM + i;
        if (m >= M) continue;
        #pragma unroll
        for (int j = 0; j < TN; j++) {
            const int n = n0 + tx*TN + j;
            if (n >= N) continue;
            float v = acc[i][j];
            if (EPI == 0) {
                v *= alpha;
            } else if (EPI == 1) {
                v = v + bias[n] + res[(long)m*ldd + n];
            } else {
                const float g = v + bias[n];
                v = 0.5f * g * (1.0f + erff(g * 0.70710678118654752f));
            }
            D[(long)m*ldd + n] = v;
        }
    }
}

// ---------------- masked softmax over one score row ------------------------
// grid: (SEQ rows, B*H). scores row has SEQP cols; cols [SEQ,SEQP) zeroed.
__global__ void softmax_kernel(float* __restrict__ scores,
                               const float* __restrict__ mask)
{
    const int r = blockIdx.x;           // 0..SEQ-1
    const int z = blockIdx.y;           // 0..B*H-1
    const int b = z >> 4;
    float* row = scores + (long)z*SEQ*SEQP + (long)r*SEQP;
    const int tid = threadIdx.x;        // 256

    float vals[5];
    float mx = -3.4e38f;
    #pragma unroll
    for (int j = 0; j < 5; j++) {
        const int i = tid + j*256;
        float v = -3.4e38f;
        if (i < SEQ) {
            v = row[i];
            if (r >= NPATCH && i < NPATCH) {
                const float mv = mask[(long)b*NQ*NPATCH + (long)(r - NPATCH)*NPATCH + i];
                if (!(mv > 0.5f)) v = NEG_BIG;
            }
        }
        vals[j] = v;
        mx = fmaxf(mx, v);
    }
    // block max
    __shared__ float sh[8];
    mx = warpMax(mx);
    const int w = tid >> 5, l = tid & 31;
    if (l == 0) sh[w] = mx;
    __syncthreads();
    if (w == 0) {
        float a = (l < 8) ? sh[l] : -3.4e38f;
        a = warpMax(a);
        if (l == 0) sh[0] = a;
    }
    __syncthreads();
    mx = sh[0];
    __syncthreads();

    float sum = 0.f;
    #pragma unroll
    for (int j = 0; j < 5; j++) {
        const int i = tid + j*256;
        if (i < SEQ) { const float e = expf(vals[j] - mx); vals[j] = e; sum += e; }
        else         { vals[j] = 0.f; }
    }
    sum = warpSum(sum);
    if (l == 0) sh[w] = sum;
    __syncthreads();
    if (w == 0) {
        float a = (l < 8) ? sh[l] : 0.f;
        a = warpSum(a);
        if (l == 0) sh[0] = a;
    }
    __syncthreads();
    const float inv = 1.0f / sh[0];

    #pragma unroll
    for (int j = 0; j < 5; j++) {
        const int i = tid + j*256;
        if (i < SEQP) row[i] = vals[j] * inv;   // pad cols get exact 0
    }
}

// ---------------- launch ----------------------------------------------------
extern "C" void kernel_launch(void* const* d_in, const int* in_sizes, int n_in,
                              void* d_out, int out_size)
{
    (void)in_sizes; (void)n_in; (void)out_size;
    const float* x      = (const float*)d_in[0];
    const float* mask   = (const float*)d_in[1];
    const float* qkv_w  = (const float*)d_in[2];
    const float* proj_w = (const float*)d_in[3];
    const float* proj_b = (const float*)d_in[4];
    const float* ln1_g  = (const float*)d_in[5];
    const float* ln1_b  = (const float*)d_in[6];
    const float* ln2_g  = (const float*)d_in[7];
    const float* ln2_b  = (const float*)d_in[8];
    const float* fc1_w  = (const float*)d_in[9];
    const float* fc1_b  = (const float*)d_in[10];
    const float* fc2_w  = (const float*)d_in[11];
    const float* fc2_b  = (const float*)d_in[12];
    float* out = (float*)d_out;

    float *p_xn, *p_qkv, *p_scores, *p_h1, *p_xmid;
    cudaGetSymbolAddress((void**)&p_xn,     g_xn);
    cudaGetSymbolAddress((void**)&p_qkv,    g_qkv);
    cudaGetSymbolAddress((void**)&p_scores, g_scores);
    cudaGetSymbolAddress((void**)&p_h1,     g_h1);
    cudaGetSymbolAddress((void**)&p_xmid,   g_xmid);

    const int MB = (MTOT + 127) / 128;   // 71
    const int SB = (SEQ + 127) / 128;    // 9

    // 1) LN1
    ln_kernel<<<MTOT, 256>>>(x, ln1_g, ln1_b, p_xn);

    // 2) qkv = xn @ qkv_w           [8992 x 3072, K=1024]
    sgemm<128,128,8,8,8,false,0><<<dim3(3*EMBED/128, MB, 1), 256>>>(
        p_xn, qkv_w, nullptr, nullptr, p_qkv,
        MTOT, 3*EMBED, EMBED, EMBED, 3*EMBED, 3*EMBED,
        0,0, 0,0, 0,0, 1.0f);

    // 3) scores = SCALE * q @ k^T   batched over 128 (b,h), [1124x1124, K=64]
    sgemm<128,128,8,8,8,true,0><<<dim3(SB, SB, BATCH*NHEADS), 256>>>(
        p_qkv, p_qkv + EMBED, nullptr, nullptr, p_scores,
        SEQ, SEQ, HDIM, 3*EMBED, 3*EMBED, SEQP,
        (long)SEQ*3*EMBED, HDIM, (long)SEQ*3*EMBED, HDIM,
        (long)NHEADS*SEQ*SEQP, (long)SEQ*SEQP, SCALE);

    // 4) masked softmax (also zeroes pad cols)
    softmax_kernel<<<dim3(SEQ, BATCH*NHEADS), 256>>>(p_scores, mask);

    // 5) attn_out = probs @ v  -> written as (b, s, h*64+d) into g_xn
    sgemm<128,64,8,8,4,false,0><<<dim3(1, SB, BATCH*NHEADS), 256>>>(
        p_scores, p_qkv + 2*EMBED, nullptr, nullptr, p_xn,
        SEQ, HDIM, SEQP, SEQP, 3*EMBED, EMBED,
        (long)NHEADS*SEQ*SEQP, (long)SEQ*SEQP,
        (long)SEQ*3*EMBED, HDIM,
        (long)SEQ*EMBED, HDIM, 1.0f);

    // 6) x_mid = attn_out @ proj_w + proj_b + x
    sgemm<128,128,8,8,8,false,1><<<dim3(EMBED/128, MB, 1), 256>>>(
        p_xn, proj_w, proj_b, x, p_xmid,
        MTOT, EMBED, EMBED, EMBED, EMBED, EMBED,
        0,0, 0,0, 0,0, 1.0f);

    // 7) LN2 (output into g_qkv scratch, which is free now)
    ln_kernel<<<MTOT, 256>>>(p_xmid, ln2_g, ln2_b, p_qkv);

    // 8) h1 = gelu(ln2 @ fc1_w + fc1_b)
    sgemm<128,128,8,8,8,false,2><<<dim3(MLPH/128, MB, 1), 256>>>(
        p_qkv, fc1_w, fc1_b, nullptr, p_h1,
        MTOT, MLPH, EMBED, EMBED, MLPH, MLPH,
        0,0, 0,0, 0,0, 1.0f);

    // 9) out = h1 @ fc2_w + fc2_b + x_mid
    sgemm<128,128,8,8,8,false,1><<<dim3(EMBED/128, MB, 1), 256>>>(
        p_h1, fc2_w, fc2_b, p_xmid, out,
        MTOT, EMBED, MLPH, MLPH, EMBED, EMBED,
        0,0, 0,0, 0,0, 1.0f);
}

// round 2
// speedup vs baseline: 1.2717x; 1.2717x over previous
#include <cuda_runtime.h>
#include <cuda_bf16.h>
#include <math.h>
#include <stdint.h>

// ---------------- problem constants ----------------
#define EMBED   1024
#define NHEADS  16
#define HDIM    64
#define SCALE   0.125f           // 64^-0.5
#define NQ      100
#define NPATCH  1024
#define SEQ     1124             // NPATCH + NQ
#define SEQP    1152             // SEQ padded
#define BATCH   8
#define MTOT    (BATCH*SEQ)      // 8992
#define MLPH    4096
#define LN_EPS  1e-6f
#define NEG_BIG (-1.0e9f)

// ---------------- scratch ----------------
__device__ float g_xn   [(MTOT+64)*EMBED];
__device__ float g_qkv  [(MTOT+64)*3*EMBED];
__device__ float g_scores[(long)BATCH*NHEADS*SEQ*SEQP];
__device__ float g_h1   [(long)MTOT*MLPH];
__device__ float g_xmid [(long)MTOT*EMBED];

// ---------------- small reductions ----------------
__device__ __forceinline__ float warpSum(float v){
    #pragma unroll
    for (int o = 16; o > 0; o >>= 1) v += __shfl_xor_sync(0xffffffffu, v, o);
    return v;
}
__device__ __forceinline__ float warpMax(float v){
    #pragma unroll
    for (int o = 16; o > 0; o >>= 1) v = fmaxf(v, __shfl_xor_sync(0xffffffffu, v, o));
    return v;
}

// ---------------- LayerNorm ----------------
__global__ void ln_kernel(const float* __restrict__ x,
                          const float* __restrict__ gamma,
                          const float* __restrict__ beta,
                          float* __restrict__ out)
{
    const int row = blockIdx.x;
    const int tid = threadIdx.x;
    const float4 v = reinterpret_cast<const float4*>(x + (size_t)row*EMBED)[tid];
    float s  = v.x + v.y + v.z + v.w;
    float ss = v.x*v.x + v.y*v.y + v.z*v.z + v.w*v.w;
    s = warpSum(s); ss = warpSum(ss);
    __shared__ float sh1[8], sh2[8];
    const int w = tid >> 5, l = tid & 31;
    if (l == 0) { sh1[w] = s; sh2[w] = ss; }
    __syncthreads();
    if (w == 0) {
        float a = (l < 8) ? sh1[l] : 0.f;
        float b = (l < 8) ? sh2[l] : 0.f;
        a = warpSum(a); b = warpSum(b);
        if (l == 0) { sh1[0] = a; sh2[0] = b; }
    }
    __syncthreads();
    const float mean = sh1[0] * (1.0f/EMBED);
    const float var  = sh2[0] * (1.0f/EMBED) - mean*mean;
    const float rstd = rsqrtf(var + LN_EPS);
    const float4 g4 = reinterpret_cast<const float4*>(gamma)[tid];
    const float4 b4 = reinterpret_cast<const float4*>(beta )[tid];
    float4 o;
    o.x = (v.x - mean)*rstd*g4.x + b4.x;
    o.y = (v.y - mean)*rstd*g4.y + b4.y;
    o.z = (v.z - mean)*rstd*g4.z + b4.z;
    o.w = (v.w - mean)*rstd*g4.w + b4.w;
    reinterpret_cast<float4*>(out + (size_t)row*EMBED)[tid] = o;
}

// ---------------- bf16x3-split tensor-core GEMM -----------------------------
// C[m,n] = epi( sum_k A[m,k]*B[k,n] ), fp32 in/out, bf16 hi/lo split compute.
// TB=true: B stored as Bp[n*ldb + k]. EPI: 0 alpha*acc; 1 +bias+res; 2 gelu(+bias)
__device__ __forceinline__ void bf16_split(float v, __nv_bfloat16& h, __nv_bfloat16& l){
    h = __float2bfloat16(v);
    l = __float2bfloat16(v - __bfloat162float(h));
}

#define MMA_BF16(c, a, b) \
    asm volatile("mma.sync.aligned.m16n8k16.row.col.f32.bf16.bf16.f32 " \
                 "{%0,%1,%2,%3},{%4,%5,%6,%7},{%8,%9},{%0,%1,%2,%3};" \
                 : "+f"(c[0]), "+f"(c[1]), "+f"(c[2]), "+f"(c[3]) \
                 : "r"(a[0]), "r"(a[1]), "r"(a[2]), "r"(a[3]), "r"(b[0]), "r"(b[1]))

template<int BM,int BN,int WM,int WN,bool TB,int EPI>
__global__ void __launch_bounds__((BM/WM)*(BN/WN)*32)
tcgemm(const float* __restrict__ Ab, const float* __restrict__ Bb,
       const float* __restrict__ bias, const float* __restrict__ res,
       float* __restrict__ Db,
       int M, int N, int K, int lda, int ldb, int ldd,
       long sAb, long sAh, long sBb, long sBh, long sDb, long sDh,
       float alpha)
{
    constexpr int BK  = 32;
    constexpr int BKP = 40;                       // pad: conflict-free frag loads
    constexpr int THREADS = (BM/WM)*(BN/WN)*32;
    constexpr int M_T = WM/16, N_T = WN/8;

    __shared__ __nv_bfloat16 Ah[BM][BKP], Al[BM][BKP];
    __shared__ __nv_bfloat16 Bh[BN][BKP], Bl[BN][BKP];

    const int tid  = threadIdx.x;
    const int lane = tid & 31;
    const int wid  = tid >> 5;
    const int wn   = wid % (BN/WN);
    const int wm   = wid / (BN/WN);

    const int z = blockIdx.z;
    const float* A = Ab + (long)(z >> 4) * sAb + (long)(z & 15) * sAh;
    const float* B = Bb + (long)(z >> 4) * sBb + (long)(z & 15) * sBh;
    float*       D = Db + (long)(z >> 4) * sDb + (long)(z & 15) * sDh;

    const int m0 = blockIdx.y * BM;
    const int n0 = blockIdx.x * BN;

    float acc[M_T][N_T][4];
    #pragma unroll
    for (int i = 0; i < M_T; i++)
        #pragma unroll
        for (int j = 0; j < N_T; j++)
            #pragma unroll
            for (int c = 0; c < 4; c++) acc[i][j][c] = 0.f;

    const int nk = K / BK;
    for (int kt = 0; kt < nk; kt++) {
        const int k0 = kt * BK;
        // ---- stage A: float4 along K, convert to hi/lo ----
        #pragma unroll
        for (int idx = tid; idx < BM*(BK/4); idx += THREADS) {
            const int row = idx / (BK/4);
            const int cg  = (idx % (BK/4)) * 4;
            float4 v = make_float4(0.f,0.f,0.f,0.f);
            if (m0 + row < M)
                v = *reinterpret_cast<const float4*>(A + (long)(m0+row)*lda + k0 + cg);
            __nv_bfloat16 h, l;
            bf16_split(v.x, h, l); Ah[row][cg+0]=h; Al[row][cg+0]=l;
            bf16_split(v.y, h, l); Ah[row][cg+1]=h; Al[row][cg+1]=l;
            bf16_split(v.z, h, l); Ah[row][cg+2]=h; Al[row][cg+2]=l;
            bf16_split(v.w, h, l); Ah[row][cg+3]=h; Al[row][cg+3]=l;
        }
        // ---- stage B into [n][k] layout ----
        if (TB) {
            #pragma unroll
            for (int idx = tid; idx < BN*(BK/4); idx += THREADS) {
                const int row = idx / (BK/4);
                const int cg  = (idx % (BK/4)) * 4;
                float4 v = make_float4(0.f,0.f,0.f,0.f);
                if (n0 + row < N)
                    v = *reinterpret_cast<const float4*>(B + (long)(n0+row)*ldb + k0 + cg);
                __nv_bfloat16 h, l;
                bf16_split(v.x, h, l); Bh[row][cg+0]=h; Bl[row][cg+0]=l;
                bf16_split(v.y, h, l); Bh[row][cg+1]=h; Bl[row][cg+1]=l;
                bf16_split(v.z, h, l); Bh[row][cg+2]=h; Bl[row][cg+2]=l;
                bf16_split(v.w, h, l); Bh[row][cg+3]=h; Bl[row][cg+3]=l;
            }
        } else {
            #pragma unroll
            for (int idx = tid; idx < BK*(BN/4); idx += THREADS) {
                const int k  = idx / (BN/4);
                const int ng = (idx % (BN/4)) * 4;
                float4 v = make_float4(0.f,0.f,0.f,0.f);
                if (n0 + ng + 3 < N)
                    v = *reinterpret_cast<const float4*>(B + (long)(k0+k)*ldb + n0 + ng);
                else {
                    if (n0+ng+0 < N) v.x = B[(long)(k0+k)*ldb + n0+ng+0];
                    if (n0+ng+1 < N) v.y = B[(long)(k0+k)*ldb + n0+ng+1];
                    if (n0+ng+2 < N) v.z = B[(long)(k0+k)*ldb + n0+ng+2];
                }
                __nv_bfloat16 h, l;
                bf16_split(v.x, h, l); Bh[ng+0][k]=h; Bl[ng+0][k]=l;
                bf16_split(v.y, h, l); Bh[ng+1][k]=h; Bl[ng+1][k]=l;
                bf16_split(v.z, h, l); Bh[ng+2][k]=h; Bl[ng+2][k]=l;
                bf16_split(v.w, h, l); Bh[ng+3][k]=h; Bl[ng+3][k]=l;
            }
        }
        __syncthreads();

        #pragma unroll
        for (int ks = 0; ks < 2; ks++) {
            const int kb = ks * 16;
            const int kc = kb + (lane & 3) * 2;
            // load all B frags (reused across i)
            uint32_t bh[N_T][2], bl[N_T][2];
            #pragma unroll
            for (int j = 0; j < N_T; j++) {
                const int col = wn*WN + j*8 + (lane >> 2);
                bh[j][0] = *reinterpret_cast<const uint32_t*>(&Bh[col][kc]);
                bh[j][1] = *reinterpret_cast<const uint32_t*>(&Bh[col][kc+8]);
                bl[j][0] = *reinterpret_cast<const uint32_t*>(&Bl[col][kc]);
                bl[j][1] = *reinterpret_cast<const uint32_t*>(&Bl[col][kc+8]);
            }
            #pragma unroll
            for (int i = 0; i < M_T; i++) {
                const int r = wm*WM + i*16 + (lane >> 2);
                uint32_t ah[4], al[4];
                ah[0] = *reinterpret_cast<const uint32_t*>(&Ah[r  ][kc]);
                ah[1] = *reinterpret_cast<const uint32_t*>(&Ah[r+8][kc]);
                ah[2] = *reinterpret_cast<const uint32_t*>(&Ah[r  ][kc+8]);
                ah[3] = *reinterpret_cast<const uint32_t*>(&Ah[r+8][kc+8]);
                al[0] = *reinterpret_cast<const uint32_t*>(&Al[r  ][kc]);
                al[1] = *reinterpret_cast<const uint32_t*>(&Al[r+8][kc]);
                al[2] = *reinterpret_cast<const uint32_t*>(&Al[r  ][kc+8]);
                al[3] = *reinterpret_cast<const uint32_t*>(&Al[r+8][kc+8]);
                #pragma unroll
                for (int j = 0; j < N_T; j++) {
                    MMA_BF16(acc[i][j], ah, bh[j]);   // hi*hi
                    MMA_BF16(acc[i][j], ah, bl[j]);   // hi*lo
                    MMA_BF16(acc[i][j], al, bh[j]);   // lo*hi
                }
            }
        }
        __syncthreads();
    }

    // ---- epilogue ----
    #pragma unroll
    for (int i = 0; i < M_T; i++) {
        #pragma unroll
        for (int j = 0; j < N_T; j++) {
            const int rbase = m0 + wm*WM + i*16 + (lane >> 2);
            const int cbase = n0 + wn*WN + j*8  + (lane & 3)*2;
            #pragma unroll
            for (int c = 0; c < 4; c++) {
                const int m = rbase + (c >= 2 ? 8 : 0);
                const int n = cbase + (c & 1);
                if (m >= M || n >= N) continue;
                float v = acc[i][j][c];
                if (EPI == 0) {
                    v *= alpha;
                } else if (EPI == 1) {
                    v = v + bias[n] + res[(long)m*ldd + n];
                } else {
                    const float g = v + bias[n];
                    v = 0.5f * g * (1.0f + erff(g * 0.70710678118654752f));
                }
                D[(long)m*ldd + n] = v;
            }
        }
    }
}

// ---------------- masked softmax ----------------
__global__ void softmax_kernel(float* __restrict__ scores,
                               const float* __restrict__ mask)
{
    const int r = blockIdx.x;
    const int z = blockIdx.y;
    const int b = z >> 4;
    float* row = scores + (long)z*SEQ*SEQP + (long)r*SEQP;
    const int tid = threadIdx.x;

    float vals[5];
    float mx = -3.4e38f;
    #pragma unroll
    for (int j = 0; j < 5; j++) {
        const int i = tid + j*256;
        float v = -3.4e38f;
        if (i < SEQ) {
            v = row[i];
            if (r >= NPATCH && i < NPATCH) {
                const float mv = mask[(long)b*NQ*NPATCH + (long)(r - NPATCH)*NPATCH + i];
                if (!(mv > 0.5f)) v = NEG_BIG;
            }
        }
        vals[j] = v;
        mx = fmaxf(mx, v);
    }
    __shared__ float sh[8];
    mx = warpMax(mx);
    const int w = tid >> 5, l = tid & 31;
    if (l == 0) sh[w] = mx;
    __syncthreads();
    if (w == 0) {
        float a = (l < 8) ? sh[l] : -3.4e38f;
        a = warpMax(a);
        if (l == 0) sh[0] = a;
    }
    __syncthreads();
    mx = sh[0];
    __syncthreads();

    float sum = 0.f;
    #pragma unroll
    for (int j = 0; j < 5; j++) {
        const int i = tid + j*256;
        if (i < SEQ) { const float e = expf(vals[j] - mx); vals[j] = e; sum += e; }
        else         { vals[j] = 0.f; }
    }
    sum = warpSum(sum);
    if (l == 0) sh[w] = sum;
    __syncthreads();
    if (w == 0) {
        float a = (l < 8) ? sh[l] : 0.f;
        a = warpSum(a);
        if (l == 0) sh[0] = a;
    }
    __syncthreads();
    const float inv = 1.0f / sh[0];

    #pragma unroll
    for (int j = 0; j < 5; j++) {
        const int i = tid + j*256;
        if (i < SEQP) row[i] = vals[j] * inv;
    }
}

// ---------------- launch ----------------
extern "C" void kernel_launch(void* const* d_in, const int* in_sizes, int n_in,
                              void* d_out, int out_size)
{
    (void)in_sizes; (void)n_in; (void)out_size;
    const float* x      = (const float*)d_in[0];
    const float* mask   = (const float*)d_in[1];
    const float* qkv_w  = (const float*)d_in[2];
    const float* proj_w = (const float*)d_in[3];
    const float* proj_b = (const float*)d_in[4];
    const float* ln1_g  = (const float*)d_in[5];
    const float* ln1_b  = (const float*)d_in[6];
    const float* ln2_g  = (const float*)d_in[7];
    const float* ln2_b  = (const float*)d_in[8];
    const float* fc1_w  = (const float*)d_in[9];
    const float* fc1_b  = (const float*)d_in[10];
    const float* fc2_w  = (const float*)d_in[11];
    const float* fc2_b  = (const float*)d_in[12];
    float* out = (float*)d_out;

    float *p_xn, *p_qkv, *p_scores, *p_h1, *p_xmid;
    cudaGetSymbolAddress((void**)&p_xn,     g_xn);
    cudaGetSymbolAddress((void**)&p_qkv,    g_qkv);
    cudaGetSymbolAddress((void**)&p_scores, g_scores);
    cudaGetSymbolAddress((void**)&p_h1,     g_h1);
    cudaGetSymbolAddress((void**)&p_xmid,   g_xmid);

    const int MB = (MTOT + 127) / 128;   // 71
    const int SB = (SEQ + 127) / 128;    // 9

    // 1) LN1
    ln_kernel<<<MTOT, 256>>>(x, ln1_g, ln1_b, p_xn);

    // 2) qkv = xn @ qkv_w
    tcgemm<128,128,64,32,false,0><<<dim3(3*EMBED/128, MB, 1), 256>>>(
        p_xn, qkv_w, nullptr, nullptr, p_qkv,
        MTOT, 3*EMBED, EMBED, EMBED, 3*EMBED, 3*EMBED,
        0,0, 0,0, 0,0, 1.0f);

    // 3) scores = SCALE * q @ k^T   (batched over 128 b,h)
    tcgemm<128,128,64,32,true,0><<<dim3(SB, SB, BATCH*NHEADS), 256>>>(
        p_qkv, p_qkv + EMBED, nullptr, nullptr, p_scores,
        SEQ, SEQ, HDIM, 3*EMBED, 3*EMBED, SEQP,
        (long)SEQ*3*EMBED, HDIM, (long)SEQ*3*EMBED, HDIM,
        (long)NHEADS*SEQ*SEQP, (long)SEQ*SEQP, SCALE);

    // 4) masked softmax (zeroes pad cols)
    softmax_kernel<<<dim3(SEQ, BATCH*NHEADS), 256>>>(p_scores, mask);

    // 5) attn_out = probs @ v  -> (b, s, h*64+d) into g_xn
    tcgemm<128,64,32,32,false,0><<<dim3(1, SB, BATCH*NHEADS), 256>>>(
        p_scores, p_qkv + 2*EMBED, nullptr, nullptr, p_xn,
        SEQ, HDIM, SEQP, SEQP, 3*EMBED, EMBED,
        (long)NHEADS*SEQ*SEQP, (long)SEQ*SEQP,
        (long)SEQ*3*EMBED, HDIM,
        (long)SEQ*EMBED, HDIM, 1.0f);

    // 6) x_mid = attn_out @ proj_w + proj_b + x
    tcgemm<128,128,64,32,false,1><<<dim3(EMBED/128, MB, 1), 256>>>(
        p_xn, proj_w, proj_b, x, p_xmid,
        MTOT, EMBED, EMBED, EMBED, EMBED, EMBED,
        0,0, 0,0, 0,0, 1.0f);

    // 7) LN2
    ln_kernel<<<MTOT, 256>>>(p_xmid, ln2_g, ln2_b, p_qkv);

    // 8) h1 = gelu(ln2 @ fc1_w + fc1_b)
    tcgemm<128,128,64,32,false,2><<<dim3(MLPH/128, MB, 1), 256>>>(
        p_qkv, fc1_w, fc1_b, nullptr, p_h1,
        MTOT, MLPH, EMBED, EMBED, MLPH, MLPH,
        0,0, 0,0, 0,0, 1.0f);

    // 9) out = h1 @ fc2_w + fc2_b + x_mid
    tcgemm<128,128,64,32,false,1><<<dim3(EMBED/128, MB, 1), 256>>>(
        p_h1, fc2_w, fc2_b, p_xmid, out,
        MTOT, EMBED, MLPH, MLPH, EMBED, EMBED,
        0,0, 0,0, 0,0, 1.0f);
}

// round 5
// speedup vs baseline: 2.9146x; 2.2920x over previous
#include <cuda_runtime.h>
#include <cuda_bf16.h>
#include <math.h>
#include <stdint.h>

using bf16 = __nv_bfloat16;

// ---------------- problem constants ----------------
#define EMBED   1024
#define NHEADS  16
#define HDIM    64
#define SCALE   0.125f
#define NQ      100
#define NPATCH  1024
#define SEQ     1124
#define SEQP    1152
#define BATCH   8
#define MTOT    (BATCH*SEQ)      // 8992
#define MLPH    4096
#define LN_EPS  1e-6f
#define NEG_BIG (-1.0e9f)

// smem bytes for a 2-stage pipeline of (Ah,Al,Bh,Bl) tiles, BKP=40
constexpr int smem_bytes(int BM, int BN) {
    return 2 /*stages*/ * (2*BM*40 + 2*BN*40) /*elems*/ * 2 /*sizeof bf16*/;
}

// ---------------- scratch ----------------
__device__ bf16  g_xn_h [MTOT*EMBED],  g_xn_l [MTOT*EMBED];     // LN1 out (reused for LN2 out)
__device__ bf16  g_qk_h [(long)MTOT*2048], g_qk_l [(long)MTOT*2048]; // q|k, ld 2048
__device__ bf16  g_vT_h [(long)BATCH*NHEADS*HDIM*SEQP], g_vT_l [(long)BATCH*NHEADS*HDIM*SEQP];
__device__ float g_scores[(long)BATCH*NHEADS*SEQ*SEQP];          // fp32 scores -> bf16 hi/lo probs in place
__device__ bf16  g_ao_h [MTOT*EMBED],  g_ao_l [MTOT*EMBED];     // attn out
__device__ bf16  g_h1_h [(long)MTOT*MLPH], g_h1_l [(long)MTOT*MLPH];
__device__ float g_xmid [(long)MTOT*EMBED];
// transposed+split weights  wT[n][k]
__device__ bf16  g_wqkv_h[(long)3072*1024], g_wqkv_l[(long)3072*1024];
__device__ bf16  g_wprj_h[(long)1024*1024], g_wprj_l[(long)1024*1024];
__device__ bf16  g_wfc1_h[(long)4096*1024], g_wfc1_l[(long)4096*1024];
__device__ bf16  g_wfc2_h[(long)1024*4096], g_wfc2_l[(long)1024*4096];

// ---------------- helpers ----------------
__device__ __forceinline__ void bf16_split(float v, bf16& h, bf16& l){
    h = __float2bfloat16(v);
    l = __float2bfloat16(v - __bfloat162float(h));
}
__device__ __forceinline__ float warpSum(float v){
    #pragma unroll
    for (int o = 16; o > 0; o >>= 1) v += __shfl_xor_sync(0xffffffffu, v, o);
    return v;
}
__device__ __forceinline__ float warpMax(float v){
    #pragma unroll
    for (int o = 16; o > 0; o >>= 1) v = fmaxf(v, __shfl_xor_sync(0xffffffffu, v, o));
    return v;
}
__device__ __forceinline__ void cp16(uint32_t s, const void* g, bool valid){
    asm volatile("cp.async.cg.shared.global [%0], [%1], 16, %2;"
                 :: "r"(s), "l"(g), "r"(valid ? 16 : 0));
}
#define CP_COMMIT() asm volatile("cp.async.commit_group;" ::: "memory")
#define CP_WAIT1()  asm volatile("cp.async.wait_group 1;" ::: "memory")

#define MMA_BF16(c, a, b) \
    asm volatile("mma.sync.aligned.m16n8k16.row.col.f32.bf16.bf16.f32 " \
                 "{%0,%1,%2,%3},{%4,%5,%6,%7},{%8,%9},{%0,%1,%2,%3};" \
                 : "+f"(c[0]), "+f"(c[1]), "+f"(c[2]), "+f"(c[3]) \
                 : "r"(a[0]), "r"(a[1]), "r"(a[2]), "r"(a[3]), "r"(b[0]), "r"(b[1]))

// ---------------- weight transpose + split: w[K][N] -> oh/ol[N][K] ---------
__global__ void wsplitT(const float* __restrict__ w, bf16* __restrict__ oh,
                        bf16* __restrict__ ol, int K, int N)
{
    __shared__ float sm[32][33];
    const int n0 = blockIdx.x*32, k0 = blockIdx.y*32;
    #pragma unroll
    for (int i = 0; i < 4; i++) {
        const int k = threadIdx.y + i*8;
        sm[k][threadIdx.x] = w[(long)(k0+k)*N + n0 + threadIdx.x];
    }
    __syncthreads();
    #pragma unroll
    for (int i = 0; i < 4; i++) {
        const int nl = threadIdx.y + i*8;
        const float v = sm[threadIdx.x][nl];
        bf16 h, l; bf16_split(v, h, l);
        const long o = (long)(n0+nl)*K + k0 + threadIdx.x;
        oh[o] = h; ol[o] = l;
    }
}

// ---------------- LayerNorm -> hi/lo bf16 ----------------
__global__ void ln_kernel(const float* __restrict__ x,
                          const float* __restrict__ gamma,
                          const float* __restrict__ beta,
                          bf16* __restrict__ oh, bf16* __restrict__ ol)
{
    const int row = blockIdx.x;
    const int tid = threadIdx.x;
    const float4 v = reinterpret_cast<const float4*>(x + (size_t)row*EMBED)[tid];
    float s  = v.x + v.y + v.z + v.w;
    float ss = v.x*v.x + v.y*v.y + v.z*v.z + v.w*v.w;
    s = warpSum(s); ss = warpSum(ss);
    __shared__ float sh1[8], sh2[8];
    const int w = tid >> 5, l = tid & 31;
    if (l == 0) { sh1[w] = s; sh2[w] = ss; }
    __syncthreads();
    if (w == 0) {
        float a = (l < 8) ? sh1[l] : 0.f;
        float b = (l < 8) ? sh2[l] : 0.f;
        a = warpSum(a); b = warpSum(b);
        if (l == 0) { sh1[0] = a; sh2[0] = b; }
    }
    __syncthreads();
    const float mean = sh1[0] * (1.0f/EMBED);
    const float var  = sh2[0] * (1.0f/EMBED) - mean*mean;
    const float rstd = rsqrtf(var + LN_EPS);
    const float4 g4 = reinterpret_cast<const float4*>(gamma)[tid];
    const float4 b4 = reinterpret_cast<const float4*>(beta )[tid];
    float o[4];
    o[0] = (v.x - mean)*rstd*g4.x + b4.x;
    o[1] = (v.y - mean)*rstd*g4.y + b4.y;
    o[2] = (v.z - mean)*rstd*g4.z + b4.z;
    o[3] = (v.w - mean)*rstd*g4.w + b4.w;
    bf16 hh[4], ll[4];
    #pragma unroll
    for (int i = 0; i < 4; i++) bf16_split(o[i], hh[i], ll[i]);
    const long base = (long)row*EMBED + tid*4;
    *reinterpret_cast<__nv_bfloat162*>(oh + base + 0) = __nv_bfloat162(hh[0], hh[1]);
    *reinterpret_cast<__nv_bfloat162*>(oh + base + 2) = __nv_bfloat162(hh[2], hh[3]);
    *reinterpret_cast<__nv_bfloat162*>(ol + base + 0) = __nv_bfloat162(ll[0], ll[1]);
    *reinterpret_cast<__nv_bfloat162*>(ol + base + 2) = __nv_bfloat162(ll[2], ll[3]);
}

// ---------------- bf16x3 tensor-core GEMM, 2-stage cp.async pipeline --------
// A: hi/lo [m][k] rows (lda), B: hi/lo [n][k] rows (ldb). BK=32.
// EPI: 0 Df=alpha*acc ; 1 Df=acc+bias+res ; 2 Dh/Dl=gelu(acc+bias)
//      3 qkv: n<2048 -> Dh/Dl (ld 2048); n>=2048 -> V transposed to Vh/Vl
//      4 Dh/Dl = acc
template<int BM,int BN,int WMW,int WNW,int EPI>
__global__ void __launch_bounds__(WMW*WNW*32)
tcgemm(const bf16* __restrict__ Ah_, const bf16* __restrict__ Al_,
       const bf16* __restrict__ Bh_, const bf16* __restrict__ Bl_,
       const float* __restrict__ bias, const float* __restrict__ res,
       float* __restrict__ Df, bf16* __restrict__ Dh, bf16* __restrict__ Dl,
       bf16* __restrict__ Vh, bf16* __restrict__ Vl,
       int M, int N, int K, int lda, int ldb, int ldd,
       long sAb, long sAh2, long sBb, long sBh2, long sDb, long sDh2,
       float alpha)
{
    constexpr int BK  = 32;
    constexpr int BKP = 40;
    constexpr int THREADS = WMW*WNW*32;
    constexpr int WM = BM/WMW, WN = BN/WNW;
    constexpr int M_T = WM/16, N_T = WN/8;
    constexpr int AS = BM*BKP, BS = BN*BKP;
    constexpr int STAGE = 2*AS + 2*BS;      // bf16 elements per stage

    extern __shared__ bf16 dsm[];

    const int tid  = threadIdx.x;
    const int lane = tid & 31;
    const int wid  = tid >> 5;
    const int wn   = wid % WNW;
    const int wm   = wid / WNW;

    const int z = blockIdx.z;
    const bf16* pAh = Ah_ + (long)(z >> 4)*sAb + (long)(z & 15)*sAh2;
    const bf16* pAl = Al_ + (long)(z >> 4)*sAb + (long)(z & 15)*sAh2;
    const bf16* pBh = Bh_ + (long)(z >> 4)*sBb + (long)(z & 15)*sBh2;
    const bf16* pBl = Bl_ + (long)(z >> 4)*sBb + (long)(z & 15)*sBh2;

    const int m0 = blockIdx.y * BM;
    const int n0 = blockIdx.x * BN;

    float acc[M_T][N_T][4];
    #pragma unroll
    for (int i = 0; i < M_T; i++)
        #pragma unroll
        for (int j = 0; j < N_T; j++)
            #pragma unroll
            for (int c = 0; c < 4; c++) acc[i][j][c] = 0.f;

    const int nk = K / BK;

    auto load_tile = [&](int st, int kt){
        const int k0 = kt * BK;
        bf16* sAh = dsm + st*STAGE;
        bf16* sAl = sAh + AS;
        bf16* sBh = sAl + AS;
        bf16* sBl = sBh + BS;
        #pragma unroll
        for (int t = 0; t < (BM*4 + THREADS - 1)/THREADS; t++) {
            const int idx = tid + t*THREADS;
            if (idx < BM*4) {
                const int row = idx >> 2, c = idx & 3;
                const int gr = m0 + row;
                const bool ok = gr < M;
                const long go = (long)(ok ? gr : 0)*lda + k0 + c*8;
                cp16((uint32_t)__cvta_generic_to_shared(sAh + row*BKP + c*8), pAh + go, ok);
                cp16((uint32_t)__cvta_generic_to_shared(sAl + row*BKP + c*8), pAl + go, ok);
            }
        }
        #pragma unroll
        for (int t = 0; t < (BN*4 + THREADS - 1)/THREADS; t++) {
            const int idx = tid + t*THREADS;
            if (idx < BN*4) {
                const int row = idx >> 2, c = idx & 3;
                const int gn = n0 + row;
                const bool ok = gn < N;
                const long go = (long)(ok ? gn : 0)*ldb + k0 + c*8;
                cp16((uint32_t)__cvta_generic_to_shared(sBh + row*BKP + c*8), pBh + go, ok);
                cp16((uint32_t)__cvta_generic_to_shared(sBl + row*BKP + c*8), pBl + go, ok);
            }
        }
    };

    load_tile(0, 0);
    CP_COMMIT();

    for (int kt = 0; kt < nk; kt++) {
        if (kt + 1 < nk) load_tile((kt+1)&1, kt+1);
        CP_COMMIT();
        CP_WAIT1();
        __syncthreads();

        const int st = kt & 1;
        const bf16* sAh = dsm + st*STAGE;
        const bf16* sAl = sAh + AS;
        const bf16* sBh = sAl + AS;
        const bf16* sBl = sBh + BS;

        #pragma unroll
        for (int ks = 0; ks < 2; ks++) {
            const int kc = ks*16 + (lane & 3)*2;
            uint32_t bh[N_T][2], bl[N_T][2];
            #pragma unroll
            for (int j = 0; j < N_T; j++) {
                const int col = wn*WN + j*8 + (lane >> 2);
                const bf16* bp = sBh + col*BKP + kc;
                bh[j][0] = *reinterpret_cast<const uint32_t*>(bp);
                bh[j][1] = *reinterpret_cast<const uint32_t*>(bp + 8);
                const bf16* bq = sBl + col*BKP + kc;
                bl[j][0] = *reinterpret_cast<const uint32_t*>(bq);
                bl[j][1] = *reinterpret_cast<const uint32_t*>(bq + 8);
            }
            #pragma unroll
            for (int i = 0; i < M_T; i++) {
                const int r = wm*WM + i*16 + (lane >> 2);
                const bf16* ap = sAh + r*BKP + kc;
                const bf16* aq = sAl + r*BKP + kc;
                uint32_t ah[4], al[4];
                ah[0] = *reinterpret_cast<const uint32_t*>(ap);
                ah[1] = *reinterpret_cast<const uint32_t*>(ap + 8*BKP);
                ah[2] = *reinterpret_cast<const uint32_t*>(ap + 8);
                ah[3] = *reinterpret_cast<const uint32_t*>(ap + 8*BKP + 8);
                al[0] = *reinterpret_cast<const uint32_t*>(aq);
                al[1] = *reinterpret_cast<const uint32_t*>(aq + 8*BKP);
                al[2] = *reinterpret_cast<const uint32_t*>(aq + 8);
                al[3] = *reinterpret_cast<const uint32_t*>(aq + 8*BKP + 8);
                #pragma unroll
                for (int j = 0; j < N_T; j++) {
                    MMA_BF16(acc[i][j], ah, bh[j]);
                    MMA_BF16(acc[i][j], ah, bl[j]);
                    MMA_BF16(acc[i][j], al, bh[j]);
                }
            }
        }
        __syncthreads();
    }

    // ---- epilogue ----
    #pragma unroll
    for (int i = 0; i < M_T; i++) {
        #pragma unroll
        for (int j = 0; j < N_T; j++) {
            #pragma unroll
            for (int h2 = 0; h2 < 2; h2++) {         // row halves (c pairs)
                const int m = m0 + wm*WM + i*16 + (lane >> 2) + h2*8;
                const int n = n0 + wn*WN + j*8  + (lane & 3)*2;
                if (m >= M || n >= N) continue;
                const float v0 = acc[i][j][h2*2 + 0];
                const float v1 = acc[i][j][h2*2 + 1];
                if (EPI == 0) {
                    float2 o = make_float2(v0*alpha, v1*alpha);
                    *reinterpret_cast<float2*>(Df + (long)(z>>4)*sDb + (long)(z&15)*sDh2 + (long)m*ldd + n) = o;
                } else if (EPI == 1) {
                    const long o = (long)m*ldd + n;
                    float2 r = *reinterpret_cast<const float2*>(res + o);
                    float2 w = make_float2(v0 + bias[n] + r.x, v1 + bias[n+1] + r.y);
                    *reinterpret_cast<float2*>(Df + o) = w;
                } else if (EPI == 2) {
                    const float g0 = v0 + bias[n],   g1 = v1 + bias[n+1];
                    const float e0 = 0.5f*g0*(1.0f + erff(g0*0.70710678118654752f));
                    const float e1 = 0.5f*g1*(1.0f + erff(g1*0.70710678118654752f));
                    bf16 h0,l0,h1,l1; bf16_split(e0,h0,l0); bf16_split(e1,h1,l1);
                    const long o = (long)m*ldd + n;
                    *reinterpret_cast<__nv_bfloat162*>(Dh + o) = __nv_bfloat162(h0, h1);
                    *reinterpret_cast<__nv_bfloat162*>(Dl + o) = __nv_bfloat162(l0, l1);
                } else if (EPI == 3) {
                    bf16 h0,l0,h1,l1; bf16_split(v0,h0,l0); bf16_split(v1,h1,l1);
                    if (n < 2048) {
                        const long o = (long)m*2048 + n;
                        *reinterpret_cast<__nv_bfloat162*>(Dh + o) = __nv_bfloat162(h0, h1);
                        *reinterpret_cast<__nv_bfloat162*>(Dl + o) = __nv_bfloat162(l0, l1);
                    } else {
                        const int b_ = m / SEQ, s_ = m % SEQ;
                        const int c0 = n - 2048;
                        const long o0 = (((long)(b_*NHEADS + (c0 >> 6)))*HDIM + (c0 & 63))*SEQP + s_;
                        const long o1 = (((long)(b_*NHEADS + ((c0+1) >> 6)))*HDIM + ((c0+1) & 63))*SEQP + s_;
                        Vh[o0] = h0; Vl[o0] = l0;
                        Vh[o1] = h1; Vl[o1] = l1;
                    }
                } else { // EPI == 4
                    bf16 h0,l0,h1,l1; bf16_split(v0,h0,l0); bf16_split(v1,h1,l1);
                    const long o = (long)(z>>4)*sDb + (long)(z&15)*sDh2 + (long)m*ldd + n;
                    *reinterpret_cast<__nv_bfloat162*>(Dh + o) = __nv_bfloat162(h0, h1);
                    *reinterpret_cast<__nv_bfloat162*>(Dl + o) = __nv_bfloat162(l0, l1);
                }
            }
        }
    }
}

// ---------------- masked softmax: fp32 row -> bf16 hi/lo in place ----------
__global__ void softmax_kernel(float* __restrict__ scores,
                               const float* __restrict__ mask)
{
    const int r = blockIdx.x;
    const int z = blockIdx.y;
    const int b = z >> 4;
    float* row = scores + (long)z*SEQ*SEQP + (long)r*SEQP;
    bf16* rh = reinterpret_cast<bf16*>(row);
    bf16* rl = rh + SEQP;
    const int tid = threadIdx.x;

    float vals[5];
    float mx = -3.4e38f;
    #pragma unroll
    for (int j = 0; j < 5; j++) {
        const int i = tid + j*256;
        float v = -3.4e38f;
        if (i < SEQ) {
            v = row[i];
            if (r >= NPATCH && i < NPATCH) {
                const float mv = mask[(long)b*NQ*NPATCH + (long)(r - NPATCH)*NPATCH + i];
                if (!(mv > 0.5f)) v = NEG_BIG;
            }
        }
        vals[j] = v;
        mx = fmaxf(mx, v);
    }
    __shared__ float sh[8];
    mx = warpMax(mx);
    const int w = tid >> 5, l = tid & 31;
    if (l == 0) sh[w] = mx;
    __syncthreads();
    if (w == 0) {
        float a = (l < 8) ? sh[l] : -3.4e38f;
        a = warpMax(a);
        if (l == 0) sh[0] = a;
    }
    __syncthreads();
    mx = sh[0];
    __syncthreads();

    float sum = 0.f;
    #pragma unroll
    for (int j = 0; j < 5; j++) {
        const int i = tid + j*256;
        if (i < SEQ) { const float e = expf(vals[j] - mx); vals[j] = e; sum += e; }
        else         { vals[j] = 0.f; }
    }
    sum = warpSum(sum);
    if (l == 0) sh[w] = sum;
    __syncthreads();
    if (w == 0) {
        float a = (l < 8) ? sh[l] : 0.f;
        a = warpSum(a);
        if (l == 0) sh[0] = a;
    }
    __syncthreads();
    const float inv = 1.0f / sh[0];

    #pragma unroll
    for (int j = 0; j < 5; j++) {
        const int i = tid + j*256;
        if (i < SEQP) {
            bf16 h, lo; bf16_split(vals[j] * inv, h, lo);
            rh[i] = h; rl[i] = lo;
        }
    }
}

// ---------------- launch ----------------
extern "C" void kernel_launch(void* const* d_in, const int* in_sizes, int n_in,
                              void* d_out, int out_size)
{
    (void)in_sizes; (void)n_in; (void)out_size;
    const float* x      = (const float*)d_in[0];
    const float* mask   = (const float*)d_in[1];
    const float* qkv_w  = (const float*)d_in[2];
    const float* proj_w = (const float*)d_in[3];
    const float* proj_b = (const float*)d_in[4];
    const float* ln1_g  = (const float*)d_in[5];
    const float* ln1_b  = (const float*)d_in[6];
    const float* ln2_g  = (const float*)d_in[7];
    const float* ln2_b  = (const float*)d_in[8];
    const float* fc1_w  = (const float*)d_in[9];
    const float* fc1_b  = (const float*)d_in[10];
    const float* fc2_w  = (const float*)d_in[11];
    const float* fc2_b  = (const float*)d_in[12];
    float* out = (float*)d_out;

    bf16 *xn_h, *xn_l, *qk_h, *qk_l, *vT_h, *vT_l, *ao_h, *ao_l, *h1_h, *h1_l;
    bf16 *wqkv_h, *wqkv_l, *wprj_h, *wprj_l, *wfc1_h, *wfc1_l, *wfc2_h, *wfc2_l;
    float *scores, *xmid;
    cudaGetSymbolAddress((void**)&xn_h, g_xn_h);   cudaGetSymbolAddress((void**)&xn_l, g_xn_l);
    cudaGetSymbolAddress((void**)&qk_h, g_qk_h);   cudaGetSymbolAddress((void**)&qk_l, g_qk_l);
    cudaGetSymbolAddress((void**)&vT_h, g_vT_h);   cudaGetSymbolAddress((void**)&vT_l, g_vT_l);
    cudaGetSymbolAddress((void**)&ao_h, g_ao_h);   cudaGetSymbolAddress((void**)&ao_l, g_ao_l);
    cudaGetSymbolAddress((void**)&h1_h, g_h1_h);   cudaGetSymbolAddress((void**)&h1_l, g_h1_l);
    cudaGetSymbolAddress((void**)&wqkv_h, g_wqkv_h); cudaGetSymbolAddress((void**)&wqkv_l, g_wqkv_l);
    cudaGetSymbolAddress((void**)&wprj_h, g_wprj_h); cudaGetSymbolAddress((void**)&wprj_l, g_wprj_l);
    cudaGetSymbolAddress((void**)&wfc1_h, g_wfc1_h); cudaGetSymbolAddress((void**)&wfc1_l, g_wfc1_l);
    cudaGetSymbolAddress((void**)&wfc2_h, g_wfc2_h); cudaGetSymbolAddress((void**)&wfc2_l, g_wfc2_l);
    cudaGetSymbolAddress((void**)&scores, g_scores);
    cudaGetSymbolAddress((void**)&xmid,   g_xmid);

    // FIXED (R4 bug): 2 stages x (2*BM*40 + 2*BN*40) elems x 2 bytes
    const int SMEM_128 = smem_bytes(128, 128);   // 81920 B
    const int SMEM_64  = smem_bytes(128, 64);    // 61440 B
    cudaFuncSetAttribute(tcgemm<128,128,2,4,0>, cudaFuncAttributeMaxDynamicSharedMemorySize, SMEM_128);
    cudaFuncSetAttribute(tcgemm<128,128,2,4,1>, cudaFuncAttributeMaxDynamicSharedMemorySize, SMEM_128);
    cudaFuncSetAttribute(tcgemm<128,128,2,4,2>, cudaFuncAttributeMaxDynamicSharedMemorySize, SMEM_128);
    cudaFuncSetAttribute(tcgemm<128,128,2,4,3>, cudaFuncAttributeMaxDynamicSharedMemorySize, SMEM_128);
    cudaFuncSetAttribute(tcgemm<128,64,4,2,4>,  cudaFuncAttributeMaxDynamicSharedMemorySize, SMEM_64);

    const int MB = (MTOT + 127) / 128;   // 71
    const int SB = (SEQ + 127) / 128;    // 9

    // 0) weight transpose+split
    wsplitT<<<dim3(3072/32, 1024/32), dim3(32,8)>>>(qkv_w,  wqkv_h, wqkv_l, 1024, 3072);
    wsplitT<<<dim3(1024/32, 1024/32), dim3(32,8)>>>(proj_w, wprj_h, wprj_l, 1024, 1024);
    wsplitT<<<dim3(4096/32, 1024/32), dim3(32,8)>>>(fc1_w,  wfc1_h, wfc1_l, 1024, 4096);
    wsplitT<<<dim3(1024/32, 4096/32), dim3(32,8)>>>(fc2_w,  wfc2_h, wfc2_l, 4096, 1024);

    // 1) LN1
    ln_kernel<<<MTOT, 256>>>(x, ln1_g, ln1_b, xn_h, xn_l);

    // 2) qkv (EPI=3): q|k -> qk (ld 2048), v -> vT
    tcgemm<128,128,2,4,3><<<dim3(3072/128, MB, 1), 256, SMEM_128>>>(
        xn_h, xn_l, wqkv_h, wqkv_l, nullptr, nullptr,
        nullptr, qk_h, qk_l, vT_h, vT_l,
        MTOT, 3072, 1024, 1024, 1024, 0,
        0,0, 0,0, 0,0, 1.0f);

    // 3) scores = SCALE * q @ k^T
    tcgemm<128,128,2,4,0><<<dim3(SB, SB, BATCH*NHEADS), 256, SMEM_128>>>(
        qk_h, qk_l, qk_h + 1024, qk_l + 1024, nullptr, nullptr,
        scores, nullptr, nullptr, nullptr, nullptr,
        SEQ, SEQ, HDIM, 2048, 2048, SEQP,
        (long)SEQ*2048, HDIM, (long)SEQ*2048, HDIM,
        (long)NHEADS*SEQ*SEQP, (long)SEQ*SEQP, SCALE);

    // 4) masked softmax -> probs hi/lo in place
    softmax_kernel<<<dim3(SEQ, BATCH*NHEADS), 256>>>(scores, mask);

    // 5) attn_out = probs @ v (EPI=4)
    tcgemm<128,64,4,2,4><<<dim3(1, SB, BATCH*NHEADS), 256, SMEM_64>>>(
        (const bf16*)scores, (const bf16*)scores + SEQP, vT_h, vT_l, nullptr, nullptr,
        nullptr, ao_h, ao_l, nullptr, nullptr,
        SEQ, HDIM, SEQP, 2*SEQP, SEQP, EMBED,
        (long)NHEADS*SEQ*2*SEQP, (long)SEQ*2*SEQP,
        (long)NHEADS*HDIM*SEQP, (long)HDIM*SEQP,
        (long)SEQ*EMBED, HDIM, 1.0f);

    // 6) x_mid = attn_out @ proj_w + proj_b + x  (EPI=1)
    tcgemm<128,128,2,4,1><<<dim3(EMBED/128, MB, 1), 256, SMEM_128>>>(
        ao_h, ao_l, wprj_h, wprj_l, proj_b, x,
        xmid, nullptr, nullptr, nullptr, nullptr,
        MTOT, EMBED, 1024, 1024, 1024, EMBED,
        0,0, 0,0, 0,0, 1.0f);

    // 7) LN2 -> xn (reuse)
    ln_kernel<<<MTOT, 256>>>(xmid, ln2_g, ln2_b, xn_h, xn_l);

    // 8) h1 = gelu(ln2 @ fc1_w + fc1_b)  (EPI=2)
    tcgemm<128,128,2,4,2><<<dim3(MLPH/128, MB, 1), 256, SMEM_128>>>(
        xn_h, xn_l, wfc1_h, wfc1_l, fc1_b, nullptr,
        nullptr, h1_h, h1_l, nullptr, nullptr,
        MTOT, MLPH, 1024, 1024, 1024, MLPH,
        0,0, 0,0, 0,0, 1.0f);

    // 9) out = h1 @ fc2_w + fc2_b + x_mid  (EPI=1)
    tcgemm<128,128,2,4,1><<<dim3(EMBED/128, MB, 1), 256, SMEM_128>>>(
        h1_h, h1_l, wfc2_h, wfc2_l, fc2_b, xmid,
        out, nullptr, nullptr, nullptr, nullptr,
        MTOT, EMBED, 4096, 4096, 4096, EMBED,
        0,0, 0,0, 0,0, 1.0f);
}

// round 7
// speedup vs baseline: 3.3609x; 1.1531x over previous
#include <cuda_runtime.h>
#include <cuda_bf16.h>
#include <math.h>
#include <stdint.h>

using bf16 = __nv_bfloat16;

// ---------------- problem constants ----------------
#define EMBED   1024
#define NHEADS  16
#define HDIM    64
#define SCALE   0.125f
#define NQ      100
#define NPATCH  1024
#define SEQ     1124
#define SEQP    1152
#define BATCH   8
#define MTOT    (BATCH*SEQ)      // 8992
#define MLPH    4096
#define LN_EPS  1e-6f
#define NEG_BIG (-1.0e9f)

// smem bytes for a 2-stage pipeline of (Ah,Al,Bh,Bl) tiles, BKP=40
constexpr int smem_bytes(int BM, int BN) {
    return 2 /*stages*/ * (2*BM*40 + 2*BN*40) /*elems*/ * 2 /*sizeof bf16*/;
}

// flash attention tile params
#define SN    64            // kv chunk
#define NCH   (SEQP/SN)     // 18
#define KVP   72            // padded ld: 144 B/row, 16B-aligned (FIX for R6 misalign)
constexpr int FLASH_SMEM = (2*128*KVP + 2*4*64*KVP) * 2;  // Q hi/lo + 2 stages x (Kh,Kl,Vh,Vl)

// ---------------- scratch ----------------
__device__ bf16  g_xn_h [MTOT*EMBED],  g_xn_l [MTOT*EMBED];     // LN1 out (reused for LN2 out)
__device__ bf16  g_qk_h [(long)MTOT*2048], g_qk_l [(long)MTOT*2048]; // q|k, ld 2048
__device__ bf16  g_vT_h [(long)BATCH*NHEADS*HDIM*SEQP], g_vT_l [(long)BATCH*NHEADS*HDIM*SEQP];
__device__ bf16  g_ao_h [MTOT*EMBED],  g_ao_l [MTOT*EMBED];     // attn out
__device__ bf16  g_h1_h [(long)MTOT*MLPH], g_h1_l [(long)MTOT*MLPH];
__device__ float g_xmid [(long)MTOT*EMBED];
// transposed+split weights  wT[n][k]
__device__ bf16  g_wqkv_h[(long)3072*1024], g_wqkv_l[(long)3072*1024];
__device__ bf16  g_wprj_h[(long)1024*1024], g_wprj_l[(long)1024*1024];
__device__ bf16  g_wfc1_h[(long)4096*1024], g_wfc1_l[(long)4096*1024];
__device__ bf16  g_wfc2_h[(long)1024*4096], g_wfc2_l[(long)1024*4096];

// ---------------- helpers ----------------
__device__ __forceinline__ void bf16_split(float v, bf16& h, bf16& l){
    h = __float2bfloat16(v);
    l = __float2bfloat16(v - __bfloat162float(h));
}
__device__ __forceinline__ float warpSum(float v){
    #pragma unroll
    for (int o = 16; o > 0; o >>= 1) v += __shfl_xor_sync(0xffffffffu, v, o);
    return v;
}
__device__ __forceinline__ void cp16(uint32_t s, const void* g, bool valid){
    asm volatile("cp.async.cg.shared.global [%0], [%1], 16, %2;"
                 :: "r"(s), "l"(g), "r"(valid ? 16 : 0));
}
#define CP_COMMIT() asm volatile("cp.async.commit_group;" ::: "memory")
#define CP_WAIT1()  asm volatile("cp.async.wait_group 1;" ::: "memory")
__device__ __forceinline__ uint32_t smaddr(const void* p){
    return (uint32_t)__cvta_generic_to_shared(p);
}
__device__ __forceinline__ uint32_t pack_bf16x2(bf16 a, bf16 b){
    __nv_bfloat162 t(a, b);
    return *reinterpret_cast<uint32_t*>(&t);
}

#define MMA_BF16(c, a, b) \
    asm volatile("mma.sync.aligned.m16n8k16.row.col.f32.bf16.bf16.f32 " \
                 "{%0,%1,%2,%3},{%4,%5,%6,%7},{%8,%9},{%0,%1,%2,%3};" \
                 : "+f"(c[0]), "+f"(c[1]), "+f"(c[2]), "+f"(c[3]) \
                 : "r"(a[0]), "r"(a[1]), "r"(a[2]), "r"(a[3]), "r"(b[0]), "r"(b[1]))

// ---------------- weight transpose + split: w[K][N] -> oh/ol[N][K] ---------
__global__ void wsplitT(const float* __restrict__ w, bf16* __restrict__ oh,
                        bf16* __restrict__ ol, int K, int N)
{
    __shared__ float sm[32][33];
    const int n0 = blockIdx.x*32, k0 = blockIdx.y*32;
    #pragma unroll
    for (int i = 0; i < 4; i++) {
        const int k = threadIdx.y + i*8;
        sm[k][threadIdx.x] = w[(long)(k0+k)*N + n0 + threadIdx.x];
    }
    __syncthreads();
    #pragma unroll
    for (int i = 0; i < 4; i++) {
        const int nl = threadIdx.y + i*8;
        const float v = sm[threadIdx.x][nl];
        bf16 h, l; bf16_split(v, h, l);
        const long o = (long)(n0+nl)*K + k0 + threadIdx.x;
        oh[o] = h; ol[o] = l;
    }
}

// ---------------- LayerNorm -> hi/lo bf16 ----------------
__global__ void ln_kernel(const float* __restrict__ x,
                          const float* __restrict__ gamma,
                          const float* __restrict__ beta,
                          bf16* __restrict__ oh, bf16* __restrict__ ol)
{
    const int row = blockIdx.x;
    const int tid = threadIdx.x;
    const float4 v = reinterpret_cast<const float4*>(x + (size_t)row*EMBED)[tid];
    float s  = v.x + v.y + v.z + v.w;
    float ss = v.x*v.x + v.y*v.y + v.z*v.z + v.w*v.w;
    s = warpSum(s); ss = warpSum(ss);
    __shared__ float sh1[8], sh2[8];
    const int w = tid >> 5, l = tid & 31;
    if (l == 0) { sh1[w] = s; sh2[w] = ss; }
    __syncthreads();
    if (w == 0) {
        float a = (l < 8) ? sh1[l] : 0.f;
        float b = (l < 8) ? sh2[l] : 0.f;
        a = warpSum(a); b = warpSum(b);
        if (l == 0) { sh1[0] = a; sh2[0] = b; }
    }
    __syncthreads();
    const float mean = sh1[0] * (1.0f/EMBED);
    const float var  = sh2[0] * (1.0f/EMBED) - mean*mean;
    const float rstd = rsqrtf(var + LN_EPS);
    const float4 g4 = reinterpret_cast<const float4*>(gamma)[tid];
    const float4 b4 = reinterpret_cast<const float4*>(beta )[tid];
    float o[4];
    o[0] = (v.x - mean)*rstd*g4.x + b4.x;
    o[1] = (v.y - mean)*rstd*g4.y + b4.y;
    o[2] = (v.z - mean)*rstd*g4.z + b4.z;
    o[3] = (v.w - mean)*rstd*g4.w + b4.w;
    bf16 hh[4], ll[4];
    #pragma unroll
    for (int i = 0; i < 4; i++) bf16_split(o[i], hh[i], ll[i]);
    const long base = (long)row*EMBED + tid*4;
    *reinterpret_cast<__nv_bfloat162*>(oh + base + 0) = __nv_bfloat162(hh[0], hh[1]);
    *reinterpret_cast<__nv_bfloat162*>(oh + base + 2) = __nv_bfloat162(hh[2], hh[3]);
    *reinterpret_cast<__nv_bfloat162*>(ol + base + 0) = __nv_bfloat162(ll[0], ll[1]);
    *reinterpret_cast<__nv_bfloat162*>(ol + base + 2) = __nv_bfloat162(ll[2], ll[3]);
}

// ---------------- bf16x3 tensor-core GEMM, 2-stage cp.async pipeline --------
// EPI: 1 Df=acc+bias+res ; 2 Dh/Dl=gelu(acc+bias) ; 3 qkv split q|k / vT
template<int BM,int BN,int WMW,int WNW,int EPI>
__global__ void __launch_bounds__(WMW*WNW*32)
tcgemm(const bf16* __restrict__ Ah_, const bf16* __restrict__ Al_,
       const bf16* __restrict__ Bh_, const bf16* __restrict__ Bl_,
       const float* __restrict__ bias, const float* __restrict__ res,
       float* __restrict__ Df, bf16* __restrict__ Dh, bf16* __restrict__ Dl,
       bf16* __restrict__ Vh, bf16* __restrict__ Vl,
       int M, int N, int K, int lda, int ldb, int ldd,
       float alpha)
{
    constexpr int BK  = 32;
    constexpr int BKP = 40;
    constexpr int THREADS = WMW*WNW*32;
    constexpr int WM = BM/WMW, WN = BN/WNW;
    constexpr int M_T = WM/16, N_T = WN/8;
    constexpr int AS = BM*BKP, BS = BN*BKP;
    constexpr int STAGE = 2*AS + 2*BS;

    extern __shared__ bf16 dsm[];

    const int tid  = threadIdx.x;
    const int lane = tid & 31;
    const int wid  = tid >> 5;
    const int wn   = wid % WNW;
    const int wm   = wid / WNW;

    const int m0 = blockIdx.y * BM;
    const int n0 = blockIdx.x * BN;

    float acc[M_T][N_T][4];
    #pragma unroll
    for (int i = 0; i < M_T; i++)
        #pragma unroll
        for (int j = 0; j < N_T; j++)
            #pragma unroll
            for (int c = 0; c < 4; c++) acc[i][j][c] = 0.f;

    const int nk = K / BK;

    auto load_tile = [&](int st, int kt){
        const int k0 = kt * BK;
        bf16* sAh = dsm + st*STAGE;
        bf16* sAl = sAh + AS;
        bf16* sBh = sAl + AS;
        bf16* sBl = sBh + BS;
        #pragma unroll
        for (int t = 0; t < (BM*4 + THREADS - 1)/THREADS; t++) {
            const int idx = tid + t*THREADS;
            if (idx < BM*4) {
                const int row = idx >> 2, c = idx & 3;
                const int gr = m0 + row;
                const bool ok = gr < M;
                const long go = (long)(ok ? gr : 0)*lda + k0 + c*8;
                cp16(smaddr(sAh + row*BKP + c*8), Ah_ + go, ok);
                cp16(smaddr(sAl + row*BKP + c*8), Al_ + go, ok);
            }
        }
        #pragma unroll
        for (int t = 0; t < (BN*4 + THREADS - 1)/THREADS; t++) {
            const int idx = tid + t*THREADS;
            if (idx < BN*4) {
                const int row = idx >> 2, c = idx & 3;
                const int gn = n0 + row;
                const bool ok = gn < N;
                const long go = (long)(ok ? gn : 0)*ldb + k0 + c*8;
                cp16(smaddr(sBh + row*BKP + c*8), Bh_ + go, ok);
                cp16(smaddr(sBl + row*BKP + c*8), Bl_ + go, ok);
            }
        }
    };

    load_tile(0, 0);
    CP_COMMIT();

    for (int kt = 0; kt < nk; kt++) {
        if (kt + 1 < nk) load_tile((kt+1)&1, kt+1);
        CP_COMMIT();
        CP_WAIT1();
        __syncthreads();

        const int st = kt & 1;
        const bf16* sAh = dsm + st*STAGE;
        const bf16* sAl = sAh + AS;
        const bf16* sBh = sAl + AS;
        const bf16* sBl = sBh + BS;

        #pragma unroll
        for (int ks = 0; ks < 2; ks++) {
            const int kc = ks*16 + (lane & 3)*2;
            uint32_t bh[N_T][2], bl[N_T][2];
            #pragma unroll
            for (int j = 0; j < N_T; j++) {
                const int col = wn*WN + j*8 + (lane >> 2);
                const bf16* bp = sBh + col*BKP + kc;
                bh[j][0] = *reinterpret_cast<const uint32_t*>(bp);
                bh[j][1] = *reinterpret_cast<const uint32_t*>(bp + 8);
                const bf16* bq = sBl + col*BKP + kc;
                bl[j][0] = *reinterpret_cast<const uint32_t*>(bq);
                bl[j][1] = *reinterpret_cast<const uint32_t*>(bq + 8);
            }
            #pragma unroll
            for (int i = 0; i < M_T; i++) {
                const int r = wm*WM + i*16 + (lane >> 2);
                const bf16* ap = sAh + r*BKP + kc;
                const bf16* aq = sAl + r*BKP + kc;
                uint32_t ah[4], al[4];
                ah[0] = *reinterpret_cast<const uint32_t*>(ap);
                ah[1] = *reinterpret_cast<const uint32_t*>(ap + 8*BKP);
                ah[2] = *reinterpret_cast<const uint32_t*>(ap + 8);
                ah[3] = *reinterpret_cast<const uint32_t*>(ap + 8*BKP + 8);
                al[0] = *reinterpret_cast<const uint32_t*>(aq);
                al[1] = *reinterpret_cast<const uint32_t*>(aq + 8*BKP);
                al[2] = *reinterpret_cast<const uint32_t*>(aq + 8);
                al[3] = *reinterpret_cast<const uint32_t*>(aq + 8*BKP + 8);
                #pragma unroll
                for (int j = 0; j < N_T; j++) {
                    MMA_BF16(acc[i][j], ah, bh[j]);
                    MMA_BF16(acc[i][j], ah, bl[j]);
                    MMA_BF16(acc[i][j], al, bh[j]);
                }
            }
        }
        __syncthreads();
    }

    // ---- epilogue ----
    #pragma unroll
    for (int i = 0; i < M_T; i++) {
        #pragma unroll
        for (int j = 0; j < N_T; j++) {
            #pragma unroll
            for (int h2 = 0; h2 < 2; h2++) {
                const int m = m0 + wm*WM + i*16 + (lane >> 2) + h2*8;
                const int n = n0 + wn*WN + j*8  + (lane & 3)*2;
                if (m >= M || n >= N) continue;
                const float v0 = acc[i][j][h2*2 + 0];
                const float v1 = acc[i][j][h2*2 + 1];
                if (EPI == 1) {
                    const long o = (long)m*ldd + n;
                    float2 r = *reinterpret_cast<const float2*>(res + o);
                    float2 w = make_float2(v0 + bias[n] + r.x, v1 + bias[n+1] + r.y);
                    *reinterpret_cast<float2*>(Df + o) = w;
                } else if (EPI == 2) {
                    const float g0 = v0 + bias[n],   g1 = v1 + bias[n+1];
                    const float e0 = 0.5f*g0*(1.0f + erff(g0*0.70710678118654752f));
                    const float e1 = 0.5f*g1*(1.0f + erff(g1*0.70710678118654752f));
                    bf16 h0,l0,h1,l1; bf16_split(e0,h0,l0); bf16_split(e1,h1,l1);
                    const long o = (long)m*ldd + n;
                    *reinterpret_cast<__nv_bfloat162*>(Dh + o) = __nv_bfloat162(h0, h1);
                    *reinterpret_cast<__nv_bfloat162*>(Dl + o) = __nv_bfloat162(l0, l1);
                } else if (EPI == 3) {
                    bf16 h0,l0,h1,l1; bf16_split(v0,h0,l0); bf16_split(v1,h1,l1);
                    if (n < 2048) {
                        const long o = (long)m*2048 + n;
                        *reinterpret_cast<__nv_bfloat162*>(Dh + o) = __nv_bfloat162(h0, h1);
                        *reinterpret_cast<__nv_bfloat162*>(Dl + o) = __nv_bfloat162(l0, l1);
                    } else {
                        const int b_ = m / SEQ, s_ = m % SEQ;
                        const int c0 = n - 2048;
                        const long o0 = (((long)(b_*NHEADS + (c0 >> 6)))*HDIM + (c0 & 63))*SEQP + s_;
                        const long o1 = (((long)(b_*NHEADS + ((c0+1) >> 6)))*HDIM + ((c0+1) & 63))*SEQP + s_;
                        Vh[o0] = h0; Vl[o0] = l0;
                        Vh[o1] = h1; Vl[o1] = l1;
                    }
                }
            }
        }
    }
}

// ---------------- fused flash attention -----------------------------------
// grid (9, B*H), block 256 (8 warps x 16 q-rows). Online masked softmax.
__global__ void __launch_bounds__(256)
flash_kernel(const bf16* __restrict__ qkh, const bf16* __restrict__ qkl,
             const bf16* __restrict__ vTh, const bf16* __restrict__ vTl,
             const float* __restrict__ mask,
             bf16* __restrict__ aoh, bf16* __restrict__ aol)
{
    extern __shared__ bf16 sm[];
    bf16* sQh = sm;
    bf16* sQl = sm + 128*KVP;
    bf16* sKV = sm + 2*128*KVP;          // [stage][Kh|Kl|Vh|Vl][64*KVP]
    const int SSTG = 4*64*KVP;

    const int tid = threadIdx.x, lane = tid & 31, wq = tid >> 5;
    const int qt = blockIdx.x;           // 0..8
    const int z  = blockIdx.y;           // b*16+h
    const int b  = z >> 4, h = z & 15;
    const int q0 = qt*128;

    // stage Q (once)
    #pragma unroll
    for (int t = 0; t < 4; t++) {
        const int idx = tid + t*256;     // 0..1023
        const int r = idx >> 3, c = idx & 7;
        long grow = (long)b*SEQ + q0 + r;
        if (grow > MTOT-1) grow = MTOT-1;
        const long go = grow*2048 + h*64 + c*8;
        cp16(smaddr(sQh + r*KVP + c*8), qkh + go, true);
        cp16(smaddr(sQl + r*KVP + c*8), qkl + go, true);
    }
    auto load_kv = [&](int st, int ci){
        const int s0 = ci*SN;
        bf16* Kh = sKV + st*SSTG;
        bf16* Kl = Kh + 64*KVP;
        bf16* Vh = Kl + 64*KVP;
        bf16* Vl = Vh + 64*KVP;
        #pragma unroll
        for (int t = 0; t < 2; t++) {
            const int idx = tid + t*256; // 0..511
            const int r = idx >> 3, c = idx & 7;
            long grow = (long)b*SEQ + s0 + r;
            if (grow > MTOT-1) grow = MTOT-1;
            const long go = grow*2048 + 1024 + h*64 + c*8;
            cp16(smaddr(Kh + r*KVP + c*8), qkh + go, true);
            cp16(smaddr(Kl + r*KVP + c*8), qkl + go, true);
            const long vo = ((long)z*HDIM + r)*SEQP + s0 + c*8;
            cp16(smaddr(Vh + r*KVP + c*8), vTh + vo, true);
            cp16(smaddr(Vl + r*KVP + c*8), vTl + vo, true);
        }
    };
    load_kv(0, 0);
    CP_COMMIT();                          // group: Q + chunk0

    uint32_t qfh[4][4], qfl[4][4];
    float Oacc[8][4];
    float m_run[2] = {-1e30f, -1e30f}, l_run[2] = {0.f, 0.f};
    #pragma unroll
    for (int j = 0; j < 8; j++)
        #pragma unroll
        for (int c = 0; c < 4; c++) Oacc[j][c] = 0.f;

    for (int ci = 0; ci < NCH; ci++) {
        if (ci + 1 < NCH) load_kv((ci+1)&1, ci+1);
        CP_COMMIT();
        CP_WAIT1();
        __syncthreads();

        if (ci == 0) {
            // Q fragments -> registers (reused every chunk)
            #pragma unroll
            for (int kk = 0; kk < 4; kk++) {
                const int r  = wq*16 + (lane >> 2);
                const int kc = kk*16 + (lane & 3)*2;
                const bf16* p = sQh + r*KVP + kc;
                qfh[kk][0] = *reinterpret_cast<const uint32_t*>(p);
                qfh[kk][1] = *reinterpret_cast<const uint32_t*>(p + 8*KVP);
                qfh[kk][2] = *reinterpret_cast<const uint32_t*>(p + 8);
                qfh[kk][3] = *reinterpret_cast<const uint32_t*>(p + 8*KVP + 8);
                const bf16* q2 = sQl + r*KVP + kc;
                qfl[kk][0] = *reinterpret_cast<const uint32_t*>(q2);
                qfl[kk][1] = *reinterpret_cast<const uint32_t*>(q2 + 8*KVP);
                qfl[kk][2] = *reinterpret_cast<const uint32_t*>(q2 + 8);
                qfl[kk][3] = *reinterpret_cast<const uint32_t*>(q2 + 8*KVP + 8);
            }
        }

        const int st = ci & 1;
        const bf16* Kh = sKV + st*SSTG;
        const bf16* Kl = Kh + 64*KVP;
        const bf16* Vh = Kl + 64*KVP;
        const bf16* Vl = Vh + 64*KVP;

        // ---- S = Q K^T ----
        float S[8][4];
        #pragma unroll
        for (int j = 0; j < 8; j++)
            #pragma unroll
            for (int c = 0; c < 4; c++) S[j][c] = 0.f;
        #pragma unroll
        for (int kk = 0; kk < 4; kk++) {
            const int kc = kk*16 + (lane & 3)*2;
            #pragma unroll
            for (int j = 0; j < 8; j++) {
                const bf16* kp = Kh + (j*8 + (lane >> 2))*KVP + kc;
                uint32_t kb[2] = { *reinterpret_cast<const uint32_t*>(kp),
                                   *reinterpret_cast<const uint32_t*>(kp + 8) };
                const bf16* kq = Kl + (j*8 + (lane >> 2))*KVP + kc;
                uint32_t kb2[2] = { *reinterpret_cast<const uint32_t*>(kq),
                                    *reinterpret_cast<const uint32_t*>(kq + 8) };
                MMA_BF16(S[j], qfh[kk], kb);
                MMA_BF16(S[j], qfh[kk], kb2);
                MMA_BF16(S[j], qfl[kk], kb);
            }
        }

        // ---- scale + bounds + mask, chunk max ----
        const int s_lane = ci*SN + (lane & 3)*2;
        float mx[2] = {m_run[0], m_run[1]};
        #pragma unroll
        for (int j = 0; j < 8; j++) {
            #pragma unroll
            for (int c = 0; c < 4; c++) {
                const int s  = s_lane + j*8 + (c & 1);
                const int ch = c >> 1;
                float v = S[j][c]*SCALE;
                if (s >= SEQ) v = -1e30f;
                else if (qt == 8) {
                    const int q = q0 + wq*16 + (lane >> 2) + ch*8;
                    if (q < SEQ && s < NPATCH) {
                        const float mv = mask[((long)b*NQ + (q - NPATCH))*NPATCH + s];
                        if (!(mv > 0.5f)) v = NEG_BIG;
                    }
                }
                S[j][c] = v;
                mx[ch] = fmaxf(mx[ch], v);
            }
        }
        #pragma unroll
        for (int ch = 0; ch < 2; ch++) {
            mx[ch] = fmaxf(mx[ch], __shfl_xor_sync(0xffffffffu, mx[ch], 1));
            mx[ch] = fmaxf(mx[ch], __shfl_xor_sync(0xffffffffu, mx[ch], 2));
        }
        float alpha[2], sum[2] = {0.f, 0.f};
        #pragma unroll
        for (int ch = 0; ch < 2; ch++) alpha[ch] = __expf(m_run[ch] - mx[ch]);
        m_run[0] = mx[0]; m_run[1] = mx[1];

        // ---- P = exp(S - m) ----
        #pragma unroll
        for (int j = 0; j < 8; j++) {
            #pragma unroll
            for (int c = 0; c < 4; c++) {
                const float p = __expf(S[j][c] - mx[c >> 1]);
                S[j][c] = p;
                sum[c >> 1] += p;
            }
        }
        #pragma unroll
        for (int ch = 0; ch < 2; ch++) {
            sum[ch] += __shfl_xor_sync(0xffffffffu, sum[ch], 1);
            sum[ch] += __shfl_xor_sync(0xffffffffu, sum[ch], 2);
            l_run[ch] = l_run[ch]*alpha[ch] + sum[ch];
        }
        #pragma unroll
        for (int j = 0; j < 8; j++) {
            #pragma unroll
            for (int c = 0; c < 4; c++) Oacc[j][c] *= alpha[c >> 1];
        }

        // ---- O += P V ----
        #pragma unroll
        for (int kk = 0; kk < 4; kk++) {
            uint32_t pah[4], pal[4];
            #pragma unroll
            for (int half = 0; half < 2; half++) {       // tiles 2kk, 2kk+1
                const int jt = 2*kk + half;
                bf16 h0,l0,h1,l1,h2,l2,h3,l3;
                bf16_split(S[jt][0], h0, l0); bf16_split(S[jt][1], h1, l1);
                bf16_split(S[jt][2], h2, l2); bf16_split(S[jt][3], h3, l3);
                pah[0 + 2*half] = pack_bf16x2(h0, h1);
                pah[1 + 2*half] = pack_bf16x2(h2, h3);
                pal[0 + 2*half] = pack_bf16x2(l0, l1);
                pal[1 + 2*half] = pack_bf16x2(l2, l3);
            }
            const int kc = kk*16 + (lane & 3)*2;
            #pragma unroll
            for (int jd = 0; jd < 8; jd++) {
                const bf16* vp = Vh + (jd*8 + (lane >> 2))*KVP + kc;
                uint32_t vb[2] = { *reinterpret_cast<const uint32_t*>(vp),
                                   *reinterpret_cast<const uint32_t*>(vp + 8) };
                const bf16* vq = Vl + (jd*8 + (lane >> 2))*KVP + kc;
                uint32_t vb2[2] = { *reinterpret_cast<const uint32_t*>(vq),
                                    *reinterpret_cast<const uint32_t*>(vq + 8) };
                MMA_BF16(Oacc[jd], pah, vb);
                MMA_BF16(Oacc[jd], pah, vb2);
                MMA_BF16(Oacc[jd], pal, vb);
            }
        }
        __syncthreads();
    }

    // ---- write out ----
    #pragma unroll
    for (int ch = 0; ch < 2; ch++) {
        const int q = q0 + wq*16 + (lane >> 2) + ch*8;
        if (q >= SEQ) continue;
        const float inv = 1.0f / l_run[ch];
        const long rowo = ((long)b*SEQ + q)*EMBED + h*64;
        #pragma unroll
        for (int jd = 0; jd < 8; jd++) {
            const int d = jd*8 + (lane & 3)*2;
            const float v0 = Oacc[jd][ch*2 + 0]*inv;
            const float v1 = Oacc[jd][ch*2 + 1]*inv;
            bf16 h0,l0,h1,l1; bf16_split(v0,h0,l0); bf16_split(v1,h1,l1);
            *reinterpret_cast<__nv_bfloat162*>(aoh + rowo + d) = __nv_bfloat162(h0, h1);
            *reinterpret_cast<__nv_bfloat162*>(aol + rowo + d) = __nv_bfloat162(l0, l1);
        }
    }
}

// ---------------- launch ----------------
extern "C" void kernel_launch(void* const* d_in, const int* in_sizes, int n_in,
                              void* d_out, int out_size)
{
    (void)in_sizes; (void)n_in; (void)out_size;
    const float* x      = (const float*)d_in[0];
    const float* mask   = (const float*)d_in[1];
    const float* qkv_w  = (const float*)d_in[2];
    const float* proj_w = (const float*)d_in[3];
    const float* proj_b = (const float*)d_in[4];
    const float* ln1_g  = (const float*)d_in[5];
    const float* ln1_b  = (const float*)d_in[6];
    const float* ln2_g  = (const float*)d_in[7];
    const float* ln2_b  = (const float*)d_in[8];
    const float* fc1_w  = (const float*)d_in[9];
    const float* fc1_b  = (const float*)d_in[10];
    const float* fc2_w  = (const float*)d_in[11];
    const float* fc2_b  = (const float*)d_in[12];
    float* out = (float*)d_out;

    bf16 *xn_h, *xn_l, *qk_h, *qk_l, *vT_h, *vT_l, *ao_h, *ao_l, *h1_h, *h1_l;
    bf16 *wqkv_h, *wqkv_l, *wprj_h, *wprj_l, *wfc1_h, *wfc1_l, *wfc2_h, *wfc2_l;
    float *xmid;
    cudaGetSymbolAddress((void**)&xn_h, g_xn_h);   cudaGetSymbolAddress((void**)&xn_l, g_xn_l);
    cudaGetSymbolAddress((void**)&qk_h, g_qk_h);   cudaGetSymbolAddress((void**)&qk_l, g_qk_l);
    cudaGetSymbolAddress((void**)&vT_h, g_vT_h);   cudaGetSymbolAddress((void**)&vT_l, g_vT_l);
    cudaGetSymbolAddress((void**)&ao_h, g_ao_h);   cudaGetSymbolAddress((void**)&ao_l, g_ao_l);
    cudaGetSymbolAddress((void**)&h1_h, g_h1_h);   cudaGetSymbolAddress((void**)&h1_l, g_h1_l);
    cudaGetSymbolAddress((void**)&wqkv_h, g_wqkv_h); cudaGetSymbolAddress((void**)&wqkv_l, g_wqkv_l);
    cudaGetSymbolAddress((void**)&wprj_h, g_wprj_h); cudaGetSymbolAddress((void**)&wprj_l, g_wprj_l);
    cudaGetSymbolAddress((void**)&wfc1_h, g_wfc1_h); cudaGetSymbolAddress((void**)&wfc1_l, g_wfc1_l);
    cudaGetSymbolAddress((void**)&wfc2_h, g_wfc2_h); cudaGetSymbolAddress((void**)&wfc2_l, g_wfc2_l);
    cudaGetSymbolAddress((void**)&xmid,   g_xmid);

    const int SMEM_128 = smem_bytes(128, 128);   // 81920 B
    cudaFuncSetAttribute(tcgemm<128,128,2,4,1>, cudaFuncAttributeMaxDynamicSharedMemorySize, SMEM_128);
    cudaFuncSetAttribute(tcgemm<128,128,2,4,2>, cudaFuncAttributeMaxDynamicSharedMemorySize, SMEM_128);
    cudaFuncSetAttribute(tcgemm<128,128,2,4,3>, cudaFuncAttributeMaxDynamicSharedMemorySize, SMEM_128);
    cudaFuncSetAttribute(flash_kernel, cudaFuncAttributeMaxDynamicSharedMemorySize, FLASH_SMEM);

    const int MB = (MTOT + 127) / 128;   // 71

    // 0) weight transpose+split
    wsplitT<<<dim3(3072/32, 1024/32), dim3(32,8)>>>(qkv_w,  wqkv_h, wqkv_l, 1024, 3072);
    wsplitT<<<dim3(1024/32, 1024/32), dim3(32,8)>>>(proj_w, wprj_h, wprj_l, 1024, 1024);
    wsplitT<<<dim3(4096/32, 1024/32), dim3(32,8)>>>(fc1_w,  wfc1_h, wfc1_l, 1024, 4096);
    wsplitT<<<dim3(1024/32, 4096/32), dim3(32,8)>>>(fc2_w,  wfc2_h, wfc2_l, 4096, 1024);

    // 1) LN1
    ln_kernel<<<MTOT, 256>>>(x, ln1_g, ln1_b, xn_h, xn_l);

    // 2) qkv (EPI=3): q|k -> qk (ld 2048), v -> vT
    tcgemm<128,128,2,4,3><<<dim3(3072/128, MB, 1), 256, SMEM_128>>>(
        xn_h, xn_l, wqkv_h, wqkv_l, nullptr, nullptr,
        nullptr, qk_h, qk_l, vT_h, vT_l,
        MTOT, 3072, 1024, 1024, 1024, 0, 1.0f);

    // 3) fused flash attention -> ao
    flash_kernel<<<dim3(9, BATCH*NHEADS), 256, FLASH_SMEM>>>(
        qk_h, qk_l, vT_h, vT_l, mask, ao_h, ao_l);

    // 4) x_mid = attn_out @ proj_w + proj_b + x  (EPI=1)
    tcgemm<128,128,2,4,1><<<dim3(EMBED/128, MB, 1), 256, SMEM_128>>>(
        ao_h, ao_l, wprj_h, wprj_l, proj_b, x,
        xmid, nullptr, nullptr, nullptr, nullptr,
        MTOT, EMBED, 1024, 1024, 1024, EMBED, 1.0f);

    // 5) LN2 -> xn (reuse)
    ln_kernel<<<MTOT, 256>>>(xmid, ln2_g, ln2_b, xn_h, xn_l);

    // 6) h1 = gelu(ln2 @ fc1_w + fc1_b)  (EPI=2)
    tcgemm<128,128,2,4,2><<<dim3(MLPH/128, MB, 1), 256, SMEM_128>>>(
        xn_h, xn_l, wfc1_h, wfc1_l, fc1_b, nullptr,
        nullptr, h1_h, h1_l, nullptr, nullptr,
        MTOT, MLPH, 1024, 1024, 1024, MLPH, 1.0f);

    // 7) out = h1 @ fc2_w + fc2_b + x_mid  (EPI=1)
    tcgemm<128,128,2,4,1><<<dim3(EMBED/128, MB, 1), 256, SMEM_128>>>(
        h1_h, h1_l, wfc2_h, wfc2_l, fc2_b, xmid,
        out, nullptr, nullptr, nullptr, nullptr,
        MTOT, EMBED, 4096, 4096, 4096, EMBED, 1.0f);
}